// round 2
// baseline (speedup 1.0000x reference)
#include <cuda_runtime.h>

#define TT 17
#define TM 16
#define DN 128
#define HH 256
#define PP 128
#define EE 32
#define MM 128
#define EPB 16   // edges per block in k_edge

// scratch (no allocations allowed)
__device__ float g_enc[TT*DN*PP];
__device__ float g_A  [TT*DN*MM];
__device__ float g_agg[TT*DN*MM];
__device__ float g_hg [TT*DN*PP];
__device__ float g_NA [TT*DN*PP];
__device__ float g_CA [TT*DN*PP];
__device__ float g_Bp [DN*DN*MM];
__device__ float g_E1 [DN*DN*PP];
__device__ int   g_nbr[DN*DN];
__device__ int   g_cnt[DN];
__device__ int   g_eIJ[DN*DN];
__device__ int   g_nE;

// ---------------------------------------------------------------- init logits
__global__ void k_init(float* out){
    int idx = blockIdx.x*blockDim.x + threadIdx.x;
    ((float4*)out)[idx] = make_float4(-1e9f,-1e9f,-1e9f,-1e9f);
}

// ---------------------------------------------------------------- neighbor + edge lists
__global__ void k_nbr(const float* __restrict__ w){
    int i = threadIdx.x;              // 128 threads
    __shared__ int cs[DN+1];
    int c = 0;
    for(int j=0;j<DN;j++) if(w[i*DN+j] > 0.f || j==i) c++;
    g_cnt[i] = c;
    cs[i+1] = c;
    __syncthreads();
    if(i==0){
        cs[0] = 0;
        for(int k=1;k<=DN;k++) cs[k] += cs[k-1];
        g_nE = cs[DN];
    }
    __syncthreads();
    int off = cs[i];
    c = 0;
    for(int j=0;j<DN;j++){
        if(w[i*DN+j] > 0.f || j==i){
            g_nbr[i*DN + c] = j;
            g_eIJ[off + c] = i*DN + j;
            c++;
        }
    }
}

// ---------------------------------------------------------------- encoder + A projection (fused)
// enc[s,d,p] = relu(x[s,:,d] @ Wn + bn);   A = enc @ Wm[:P]
__global__ void k_encA(const float* __restrict__ x, const float* __restrict__ Wn,
                       const float* __restrict__ bn, const float* __restrict__ Wm){
    int d0 = blockIdx.x*8, s = blockIdx.y, p = threadIdx.x;
    __shared__ float xr[8][HH];
    __shared__ float hs[8][PP];
    for(int it=p; it<8*HH; it+=128){
        int h = it>>3, r = it&7;
        xr[r][h] = x[(s*HH+h)*DN + d0 + r];
    }
    __syncthreads();
    float acc[8];
    float b = bn[p];
    #pragma unroll
    for(int r=0;r<8;r++) acc[r] = b;
    #pragma unroll 4
    for(int k=0;k<HH;k+=4){
        float w0=Wn[(k  )*PP+p], w1=Wn[(k+1)*PP+p];
        float w2=Wn[(k+2)*PP+p], w3=Wn[(k+3)*PP+p];
        #pragma unroll
        for(int r=0;r<8;r++){
            float4 xv = *(const float4*)&xr[r][k];
            acc[r]=fmaf(xv.x,w0,acc[r]); acc[r]=fmaf(xv.y,w1,acc[r]);
            acc[r]=fmaf(xv.z,w2,acc[r]); acc[r]=fmaf(xv.w,w3,acc[r]);
        }
    }
    #pragma unroll
    for(int r=0;r<8;r++){
        float v = fmaxf(acc[r], 0.f);
        g_enc[(s*DN+d0+r)*PP+p] = v;
        hs[r][p] = v;
    }
    __syncthreads();
    float a2[8];
    #pragma unroll
    for(int r=0;r<8;r++) a2[r] = 0.f;
    #pragma unroll 4
    for(int k=0;k<PP;k+=4){
        float w0=Wm[(k  )*MM+p], w1=Wm[(k+1)*MM+p];
        float w2=Wm[(k+2)*MM+p], w3=Wm[(k+3)*MM+p];
        #pragma unroll
        for(int r=0;r<8;r++){
            float4 hv = *(const float4*)&hs[r][k];
            a2[r]=fmaf(hv.x,w0,a2[r]); a2[r]=fmaf(hv.y,w1,a2[r]);
            a2[r]=fmaf(hv.z,w2,a2[r]); a2[r]=fmaf(hv.w,w3,a2[r]);
        }
    }
    #pragma unroll
    for(int r=0;r<8;r++) g_A[(s*DN+d0+r)*MM+p] = a2[r];
}

// ---------------------------------------------------------------- per-edge encodings (flat list)
// Bp = v@Wm[P:] + bm;  E1 = v@Wc1[2P:] + bc1 ;  v = relu(w*We + be)
__global__ void __launch_bounds__(256) k_edge(
        const float* __restrict__ w,  const float* __restrict__ We,
        const float* __restrict__ be, const float* __restrict__ Wm,
        const float* __restrict__ bm, const float* __restrict__ Wc1,
        const float* __restrict__ bc1){
    int nE = g_nE;
    int e0 = blockIdx.x * EPB;
    if(e0 >= nE) return;
    int tid = threadIdx.x;
    __shared__ float vs[EE][EPB];
    __shared__ float ws[EPB];
    __shared__ int   ij[EPB];
    int nv = min(EPB, nE - e0);
    if(tid < EPB){
        int pr = g_eIJ[e0 + ((tid < nv) ? tid : 0)];
        ij[tid] = pr;
        ws[tid] = w[pr];
    }
    __syncthreads();
    for(int it=tid; it<EE*EPB; it+=256){
        int k = it>>4, r = it&15;
        vs[k][r] = fmaxf(fmaf(ws[r], We[k], be[k]), 0.f);
    }
    __syncthreads();
    int col = tid & 127;
    bool isB = tid < 128;
    const float* Wt = isB ? (Wm + PP*MM + col) : (Wc1 + 2*PP*PP + col);
    float bias = isB ? bm[col] : bc1[col];
    float acc[EPB];
    #pragma unroll
    for(int r=0;r<EPB;r++) acc[r] = bias;
    #pragma unroll
    for(int k=0;k<EE;k++){
        float wt = Wt[k*128];
        float4 v0 = ((const float4*)vs[k])[0];
        float4 v1 = ((const float4*)vs[k])[1];
        float4 v2 = ((const float4*)vs[k])[2];
        float4 v3 = ((const float4*)vs[k])[3];
        acc[0]=fmaf(v0.x,wt,acc[0]);  acc[1]=fmaf(v0.y,wt,acc[1]);
        acc[2]=fmaf(v0.z,wt,acc[2]);  acc[3]=fmaf(v0.w,wt,acc[3]);
        acc[4]=fmaf(v1.x,wt,acc[4]);  acc[5]=fmaf(v1.y,wt,acc[5]);
        acc[6]=fmaf(v1.z,wt,acc[6]);  acc[7]=fmaf(v1.w,wt,acc[7]);
        acc[8]=fmaf(v2.x,wt,acc[8]);  acc[9]=fmaf(v2.y,wt,acc[9]);
        acc[10]=fmaf(v2.z,wt,acc[10]); acc[11]=fmaf(v2.w,wt,acc[11]);
        acc[12]=fmaf(v3.x,wt,acc[12]); acc[13]=fmaf(v3.y,wt,acc[13]);
        acc[14]=fmaf(v3.z,wt,acc[14]); acc[15]=fmaf(v3.w,wt,acc[15]);
    }
    float* dst = isB ? g_Bp : g_E1;
    for(int r=0;r<nv;r++) dst[ij[r]*MM + col] = acc[r];
}

// ---------------------------------------------------------------- message aggregation
__global__ void k_agg(){
    int i = blockIdx.x, m = threadIdx.x;
    float acc[TT];
    #pragma unroll
    for(int s=0;s<TT;s++) acc[s] = 0.f;
    int cnt = g_cnt[i];
    for(int k=0;k<cnt;k++){
        int j = g_nbr[i*DN + k];
        float b = g_Bp[(i*DN + j)*MM + m];
        int base = j*MM + m;
        #pragma unroll
        for(int s=0;s<TT;s++)
            acc[s] = fmaxf(acc[s], g_A[s*DN*MM + base] + b);
    }
    #pragma unroll
    for(int s=0;s<TT;s++) g_agg[(s*DN + i)*MM + m] = acc[s];
}

// ---------------------------------------------------------------- update + gate + NA/CA (fused)
__global__ void k_updnc(const float* __restrict__ Wu, const float* __restrict__ bu,
                        const float* __restrict__ Wg, const float* __restrict__ bg,
                        const float* __restrict__ Wc1){
    int d0 = blockIdx.x*8, s = blockIdx.y, p = threadIdx.x;
    __shared__ float cat[8][PP+MM];
    __shared__ float hs[8][PP];
    for(int it=p; it<8*PP; it+=128){
        int q = it>>3, r = it&7;
        cat[r][q]    = g_enc[(s*DN+d0+r)*PP+q];
        cat[r][PP+q] = g_agg[(s*DN+d0+r)*MM+q];
    }
    __syncthreads();
    float u[8], g[8];
    float bup = bu[p], bgp = bg[p];
    #pragma unroll
    for(int r=0;r<8;r++){ u[r]=bup; g[r]=bgp; }
    #pragma unroll 2
    for(int k=0;k<PP+MM;k+=4){
        float u0=Wu[(k)*PP+p], u1=Wu[(k+1)*PP+p], u2=Wu[(k+2)*PP+p], u3=Wu[(k+3)*PP+p];
        float g0=Wg[(k)*PP+p], g1=Wg[(k+1)*PP+p], g2=Wg[(k+2)*PP+p], g3=Wg[(k+3)*PP+p];
        #pragma unroll
        for(int r=0;r<8;r++){
            float4 c = *(const float4*)&cat[r][k];
            u[r]=fmaf(c.x,u0,u[r]); u[r]=fmaf(c.y,u1,u[r]);
            u[r]=fmaf(c.z,u2,u[r]); u[r]=fmaf(c.w,u3,u[r]);
            g[r]=fmaf(c.x,g0,g[r]); g[r]=fmaf(c.y,g1,g[r]);
            g[r]=fmaf(c.z,g2,g[r]); g[r]=fmaf(c.w,g3,g[r]);
        }
    }
    #pragma unroll
    for(int r=0;r<8;r++){
        float up = fmaxf(u[r], 0.f);
        float gg = 1.f / (1.f + __expf(-g[r]));
        float hv = gg*up + (1.f - gg)*cat[r][p];
        g_hg[(s*DN+d0+r)*PP+p] = hv;
        hs[r][p] = hv;
    }
    __syncthreads();
    float a1[8], a2[8];
    #pragma unroll
    for(int r=0;r<8;r++){ a1[r]=0.f; a2[r]=0.f; }
    #pragma unroll 2
    for(int k=0;k<PP;k+=4){
        float n0=Wc1[(k)*PP+p], n1=Wc1[(k+1)*PP+p], n2=Wc1[(k+2)*PP+p], n3=Wc1[(k+3)*PP+p];
        float c0=Wc1[(PP+k)*PP+p], c1=Wc1[(PP+k+1)*PP+p], c2=Wc1[(PP+k+2)*PP+p], c3=Wc1[(PP+k+3)*PP+p];
        #pragma unroll
        for(int r=0;r<8;r++){
            float4 h = *(const float4*)&hs[r][k];
            a1[r]=fmaf(h.x,n0,a1[r]); a1[r]=fmaf(h.y,n1,a1[r]);
            a1[r]=fmaf(h.z,n2,a1[r]); a1[r]=fmaf(h.w,n3,a1[r]);
            a2[r]=fmaf(h.x,c0,a2[r]); a2[r]=fmaf(h.y,c1,a2[r]);
            a2[r]=fmaf(h.z,c2,a2[r]); a2[r]=fmaf(h.w,c3,a2[r]);
        }
    }
    #pragma unroll
    for(int r=0;r<8;r++){
        g_NA[(s*DN+d0+r)*PP+p] = a1[r];
        g_CA[(s*DN+d0+r)*PP+p] = a2[r];
    }
}

// ---------------------------------------------------------------- logits (sparse pairs, t inner)
__global__ void __launch_bounds__(256) k_logits(const float* __restrict__ Wc2,
                                                const float* __restrict__ bc2,
                                                float* __restrict__ out){
    int i = blockIdx.x;
    int lane = threadIdx.x & 31, wp = threadIdx.x >> 5;   // 8 warps
    float4 wc = *(const float4*)&Wc2[lane*4];
    float bc2v = bc2[0];
    float4 na[TM];
    #pragma unroll
    for(int t=0;t<TM;t++) na[t] = *(const float4*)&g_NA[((t+1)*DN + i)*PP + lane*4];
    int cnt = g_cnt[i];
    for(int k=wp; k<cnt; k+=8){
        int j = g_nbr[i*DN + k];
        float4 e1 = *(const float4*)&g_E1[(i*DN + j)*PP + lane*4];
        #pragma unroll
        for(int t=0;t<TM;t++){
            float4 ca = *(const float4*)&g_CA[(t*DN + j)*PP + lane*4];
            float s;
            s  = fmaxf(na[t].x + ca.x + e1.x, 0.f) * wc.x;
            s += fmaxf(na[t].y + ca.y + e1.y, 0.f) * wc.y;
            s += fmaxf(na[t].z + ca.z + e1.z, 0.f) * wc.z;
            s += fmaxf(na[t].w + ca.w + e1.w, 0.f) * wc.w;
            #pragma unroll
            for(int off=16; off; off>>=1) s += __shfl_xor_sync(0xffffffffu, s, off);
            if(lane == 0) out[t*DN*DN + i*DN + j] = s + bc2v;
        }
    }
}

// ---------------------------------------------------------------- dist head
__global__ void k_dist(const float* __restrict__ Wd1, const float* __restrict__ bd1,
                       const float* __restrict__ Wd2, const float* __restrict__ bd2,
                       float* __restrict__ out){
    int d0 = blockIdx.x*8, t = blockIdx.y, p = threadIdx.x;
    __shared__ float df[8][2*PP];
    __shared__ float red[8][PP];
    for(int it=p; it<8*PP; it+=128){
        int q = it>>3, r = it&7;
        df[r][q]    = g_hg[( t    *DN + d0+r)*PP + q];
        df[r][PP+q] = g_hg[((t+1)*DN + d0+r)*PP + q];
    }
    __syncthreads();
    float acc[8];
    float b = bd1[p];
    #pragma unroll
    for(int r=0;r<8;r++) acc[r] = b;
    #pragma unroll 2
    for(int k=0;k<2*PP;k+=4){
        float w0=Wd1[(k)*PP+p], w1=Wd1[(k+1)*PP+p], w2=Wd1[(k+2)*PP+p], w3=Wd1[(k+3)*PP+p];
        #pragma unroll
        for(int r=0;r<8;r++){
            float4 c = *(const float4*)&df[r][k];
            acc[r]=fmaf(c.x,w0,acc[r]); acc[r]=fmaf(c.y,w1,acc[r]);
            acc[r]=fmaf(c.z,w2,acc[r]); acc[r]=fmaf(c.w,w3,acc[r]);
        }
    }
    float wd = Wd2[p];
    #pragma unroll
    for(int r=0;r<8;r++) red[r][p] = fmaxf(acc[r], 0.f) * wd;
    __syncthreads();
    int wp = p >> 5, lane = p & 31;
    #pragma unroll
    for(int rr=0; rr<2; rr++){
        int r = wp*2 + rr;
        float sv = red[r][lane] + red[r][lane+32] + red[r][lane+64] + red[r][lane+96];
        #pragma unroll
        for(int off=16; off; off>>=1) sv += __shfl_xor_sync(0xffffffffu, sv, off);
        if(lane == 0) out[TM*DN*DN + t*DN + d0 + r] = sv + bd2[0];
    }
}

// ---------------------------------------------------------------- host launcher
extern "C" void kernel_launch(void* const* d_in, const int* in_sizes, int n_in,
                              void* d_out, int out_size){
    struct Exp { int sz; bool opt; };
    static const Exp exp_[23] = {
        {557056,false}, // x
        {16384 ,false}, // edge_w
        {128   ,true }, // batch
        {1     ,true }, // no_graphs
        {2     ,true }, // time_i
        {32768 ,false},{128,false},          // Wn, bn
        {32    ,false},{32 ,false},          // We, be
        {20480 ,false},{128,false},          // Wm, bm
        {32768 ,false},{128,false},          // Wu, bu
        {32768 ,false},{128,false},          // Wg, bg
        {36864 ,false},{128,false},          // Wc1, bc1
        {128   ,false},{1  ,false},          // Wc2, bc2
        {32768 ,false},{128,false},          // Wd1, bd1
        {128   ,false},{1  ,false},          // Wd2, bd2
    };
    const void* ptr[23] = {};
    int pos = 0;
    for(int e=0;e<23;e++){
        if(pos < n_in && in_sizes[pos] == exp_[e].sz){ ptr[e] = d_in[pos]; pos++; }
        else if(exp_[e].opt){ ptr[e] = nullptr; }
        else if(pos < n_in){ ptr[e] = d_in[pos]; pos++; }
    }
    const float* x    = (const float*)ptr[0];
    const float* ew   = (const float*)ptr[1];
    const float* Wn   = (const float*)ptr[5];
    const float* bn   = (const float*)ptr[6];
    const float* We   = (const float*)ptr[7];
    const float* be   = (const float*)ptr[8];
    const float* Wm   = (const float*)ptr[9];
    const float* bm   = (const float*)ptr[10];
    const float* Wu   = (const float*)ptr[11];
    const float* bu   = (const float*)ptr[12];
    const float* Wg   = (const float*)ptr[13];
    const float* bg   = (const float*)ptr[14];
    const float* Wc1  = (const float*)ptr[15];
    const float* bc1  = (const float*)ptr[16];
    const float* Wc2  = (const float*)ptr[17];
    const float* bc2  = (const float*)ptr[18];
    const float* Wd1  = (const float*)ptr[19];
    const float* bd1  = (const float*)ptr[20];
    const float* Wd2  = (const float*)ptr[21];
    const float* bd2  = (const float*)ptr[22];
    float* out = (float*)d_out;

    k_init  <<<512, 128>>>(out);
    k_nbr   <<<1, 128>>>(ew);
    k_encA  <<<dim3(DN/8, TT), 128>>>(x, Wn, bn, Wm);
    k_edge  <<<DN*DN/EPB, 256>>>(ew, We, be, Wm, bm, Wc1, bc1);
    k_agg   <<<DN, 128>>>();
    k_updnc <<<dim3(DN/8, TT), 128>>>(Wu, bu, Wg, bg, Wc1);
    k_logits<<<DN, 256>>>(Wc2, bc2, out);
    k_dist  <<<dim3(DN/8, TM), 128>>>(Wd1, bd1, Wd2, bd2, out);
}

// round 3
// speedup vs baseline: 1.2365x; 1.2365x over previous
#include <cuda_runtime.h>

#define TT 17
#define TM 16
#define DN 128
#define HH 256
#define PP 128
#define EE 32
#define MM 128

// scratch (no allocations allowed)
__device__ float g_enc[TT*DN*PP];
__device__ float g_A  [TT*DN*MM];
__device__ float g_agg[TT*DN*MM];
__device__ float g_hg [TT*DN*PP];
__device__ float g_NA [TT*DN*PP];
__device__ float g_CA [TT*DN*PP];
__device__ float g_Bp [DN*DN*MM];   // fallback only
__device__ float g_E1 [DN*DN*PP];   // fallback only
__device__ float g_U  [MM];
__device__ float g_V  [PP];
__device__ int   g_nbr[DN*DN];
__device__ float g_nw [DN*DN];
__device__ int   g_cnt[DN];
__device__ int   g_flag;

// ---------------------------------------------------------------- init logits to -1e9
__global__ void k_init(float* out){
    int idx = blockIdx.x*blockDim.x + threadIdx.x;
    ((float4*)out)[idx] = make_float4(-1e9f,-1e9f,-1e9f,-1e9f);
}

// ---------------------------------------------------------------- neighbor lists (parallel, ballot compaction)
__global__ void k_nbr(const float* __restrict__ w){
    int i = blockIdx.x, j = threadIdx.x;          // 128 threads
    float wv = w[i*DN + j];
    bool pred = (wv > 0.f) || (j == i);
    unsigned m = __ballot_sync(0xffffffffu, pred);
    int lane = j & 31, wp = j >> 5;
    __shared__ int wc[4];
    if(lane == 0) wc[wp] = __popc(m);
    __syncthreads();
    int off = 0;
    for(int t=0;t<wp;t++) off += wc[t];
    if(pred){
        int pos = off + __popc(m & ((1u<<lane)-1u));
        g_nbr[i*DN + pos] = j;
        g_nw [i*DN + pos] = wv;
    }
    if(j == 127) g_cnt[i] = off + __popc(m);
}

// ---------------------------------------------------------------- rank-1 edge precompute + flag
__global__ void k_prep(const float* __restrict__ We, const float* __restrict__ be,
                       const float* __restrict__ Wm, const float* __restrict__ Wc1){
    int p = threadIdx.x;                           // 128 threads
    __shared__ float wes[EE];
    __shared__ int bad;
    if(p == 0) bad = 0;
    __syncthreads();
    if(p < EE){
        wes[p] = fmaxf(We[p], 0.f);
        if(be[p] != 0.f) atomicAdd(&bad, 1);
    }
    __syncthreads();
    float u = 0.f, v = 0.f;
    #pragma unroll
    for(int e=0;e<EE;e++){
        float s = wes[e];
        u = fmaf(s, Wm [(PP  + e)*MM + p], u);
        v = fmaf(s, Wc1[(2*PP+ e)*PP + p], v);
    }
    g_U[p] = u;
    g_V[p] = v;
    if(p == 0) g_flag = (bad == 0) ? 1 : 0;
}

// ---------------------------------------------------------------- fallback (only if be != 0; never in practice)
__global__ void k_edgeF(const float* __restrict__ We, const float* __restrict__ be,
                        const float* __restrict__ Wm, const float* __restrict__ bm,
                        const float* __restrict__ Wc1,const float* __restrict__ bc1){
    if(g_flag) return;
    int i = blockIdx.x, tid = threadIdx.x;         // 256 threads
    int col = tid & 127;
    bool isB = tid < 128;
    const float* Wt = isB ? (Wm + PP*MM + col) : (Wc1 + 2*PP*PP + col);
    float bias = isB ? bm[col] : bc1[col];
    __shared__ float vs[EE];
    int cnt = g_cnt[i];
    for(int k=0;k<cnt;k++){
        int j = g_nbr[i*DN + k];
        float wv = g_nw[i*DN + k];
        if(tid < EE) vs[tid] = fmaxf(fmaf(wv, We[tid], be[tid]), 0.f);
        __syncthreads();
        float a = bias;
        #pragma unroll
        for(int e=0;e<EE;e++) a = fmaf(vs[e], Wt[e*128], a);
        (isB ? g_Bp : g_E1)[(i*DN + j)*MM + col] = a;
        __syncthreads();
    }
}

// ---------------------------------------------------------------- encoder + A projection (fused, 256 thr)
__global__ void __launch_bounds__(256) k_encA(
        const float* __restrict__ x, const float* __restrict__ Wn,
        const float* __restrict__ bn, const float* __restrict__ Wm){
    int d0 = blockIdx.x*8, s = blockIdx.y;
    int tid = threadIdx.x, p = tid & 127, hf = tid >> 7;   // hf handles rows hf*4..hf*4+3
    __shared__ float xr[8][HH];
    __shared__ float hs[8][PP];
    for(int it=tid; it<8*HH; it+=256){
        int h = it>>3, r = it&7;
        xr[r][h] = x[(s*HH+h)*DN + d0 + r];
    }
    __syncthreads();
    float acc[4];
    float b = bn[p];
    #pragma unroll
    for(int r=0;r<4;r++) acc[r] = b;
    #pragma unroll 4
    for(int k=0;k<HH;k+=4){
        float w0=Wn[(k  )*PP+p], w1=Wn[(k+1)*PP+p];
        float w2=Wn[(k+2)*PP+p], w3=Wn[(k+3)*PP+p];
        #pragma unroll
        for(int rr=0;rr<4;rr++){
            float4 xv = *(const float4*)&xr[hf*4+rr][k];
            acc[rr]=fmaf(xv.x,w0,acc[rr]); acc[rr]=fmaf(xv.y,w1,acc[rr]);
            acc[rr]=fmaf(xv.z,w2,acc[rr]); acc[rr]=fmaf(xv.w,w3,acc[rr]);
        }
    }
    #pragma unroll
    for(int rr=0;rr<4;rr++){
        float v = fmaxf(acc[rr], 0.f);
        g_enc[(s*DN+d0+hf*4+rr)*PP+p] = v;
        hs[hf*4+rr][p] = v;
    }
    __syncthreads();
    float a2[4];
    #pragma unroll
    for(int rr=0;rr<4;rr++) a2[rr] = 0.f;
    #pragma unroll 4
    for(int k=0;k<PP;k+=4){
        float w0=Wm[(k  )*MM+p], w1=Wm[(k+1)*MM+p];
        float w2=Wm[(k+2)*MM+p], w3=Wm[(k+3)*MM+p];
        #pragma unroll
        for(int rr=0;rr<4;rr++){
            float4 hv = *(const float4*)&hs[hf*4+rr][k];
            a2[rr]=fmaf(hv.x,w0,a2[rr]); a2[rr]=fmaf(hv.y,w1,a2[rr]);
            a2[rr]=fmaf(hv.z,w2,a2[rr]); a2[rr]=fmaf(hv.w,w3,a2[rr]);
        }
    }
    #pragma unroll
    for(int rr=0;rr<4;rr++) g_A[(s*DN+d0+hf*4+rr)*MM+p] = a2[rr];
}

// ---------------------------------------------------------------- message aggregation (s-split)
__global__ void k_agg(const float* __restrict__ bm){
    int i = blockIdx.x, m = threadIdx.x;
    int s0 = blockIdx.y * 9;
    int ns = (blockIdx.y == 0) ? 9 : 8;
    float acc[9];
    #pragma unroll
    for(int ss=0;ss<9;ss++) acc[ss] = 0.f;
    int cnt = g_cnt[i];
    int flag = g_flag;
    float Um = g_U[m], bmm = bm[m];
    __shared__ int   js[DN];
    __shared__ float ws[DN];
    for(int it=m; it<cnt; it+=128){ js[it]=g_nbr[i*DN+it]; ws[it]=g_nw[i*DN+it]; }
    __syncthreads();
    if(flag){
        for(int k=0;k<cnt;k++){
            int j = js[k];
            float b = fmaf(ws[k], Um, bmm);
            int base = j*MM + m;
            #pragma unroll
            for(int ss=0;ss<9;ss++)
                if(ss < ns) acc[ss] = fmaxf(acc[ss], g_A[(s0+ss)*DN*MM + base] + b);
        }
    }else{
        for(int k=0;k<cnt;k++){
            int j = js[k];
            float b = g_Bp[(i*DN + j)*MM + m];
            int base = j*MM + m;
            #pragma unroll
            for(int ss=0;ss<9;ss++)
                if(ss < ns) acc[ss] = fmaxf(acc[ss], g_A[(s0+ss)*DN*MM + base] + b);
        }
    }
    for(int ss=0;ss<ns;ss++) g_agg[((s0+ss)*DN + i)*MM + m] = acc[ss];
}

// ---------------------------------------------------------------- update + gate + NA/CA (fused, 256 thr)
__global__ void __launch_bounds__(256) k_updnc(
        const float* __restrict__ Wu, const float* __restrict__ bu,
        const float* __restrict__ Wg, const float* __restrict__ bg,
        const float* __restrict__ Wc1){
    int d0 = blockIdx.x*8, s = blockIdx.y;
    int tid = threadIdx.x, p = tid & 127, hf = tid >> 7;
    __shared__ float cat[8][PP+MM];
    __shared__ float hs[8][PP];
    for(int it=tid; it<8*PP; it+=256){
        int q = it>>3, r = it&7;
        cat[r][q]    = g_enc[(s*DN+d0+r)*PP+q];
        cat[r][PP+q] = g_agg[(s*DN+d0+r)*MM+q];
    }
    __syncthreads();
    float u[4], g[4];
    float bup = bu[p], bgp = bg[p];
    #pragma unroll
    for(int r=0;r<4;r++){ u[r]=bup; g[r]=bgp; }
    #pragma unroll 2
    for(int k=0;k<PP+MM;k+=4){
        float u0=Wu[(k)*PP+p], u1=Wu[(k+1)*PP+p], u2=Wu[(k+2)*PP+p], u3=Wu[(k+3)*PP+p];
        float g0=Wg[(k)*PP+p], g1=Wg[(k+1)*PP+p], g2=Wg[(k+2)*PP+p], g3=Wg[(k+3)*PP+p];
        #pragma unroll
        for(int rr=0;rr<4;rr++){
            float4 c = *(const float4*)&cat[hf*4+rr][k];
            u[rr]=fmaf(c.x,u0,u[rr]); u[rr]=fmaf(c.y,u1,u[rr]);
            u[rr]=fmaf(c.z,u2,u[rr]); u[rr]=fmaf(c.w,u3,u[rr]);
            g[rr]=fmaf(c.x,g0,g[rr]); g[rr]=fmaf(c.y,g1,g[rr]);
            g[rr]=fmaf(c.z,g2,g[rr]); g[rr]=fmaf(c.w,g3,g[rr]);
        }
    }
    #pragma unroll
    for(int rr=0;rr<4;rr++){
        int r = hf*4+rr;
        float up = fmaxf(u[rr], 0.f);
        float gg = 1.f / (1.f + __expf(-g[rr]));
        float hv = gg*up + (1.f - gg)*cat[r][p];
        g_hg[(s*DN+d0+r)*PP+p] = hv;
        hs[r][p] = hv;
    }
    __syncthreads();
    float a1[4], a2[4];
    #pragma unroll
    for(int r=0;r<4;r++){ a1[r]=0.f; a2[r]=0.f; }
    #pragma unroll 2
    for(int k=0;k<PP;k+=4){
        float n0=Wc1[(k)*PP+p], n1=Wc1[(k+1)*PP+p], n2=Wc1[(k+2)*PP+p], n3=Wc1[(k+3)*PP+p];
        float c0=Wc1[(PP+k)*PP+p], c1=Wc1[(PP+k+1)*PP+p], c2=Wc1[(PP+k+2)*PP+p], c3=Wc1[(PP+k+3)*PP+p];
        #pragma unroll
        for(int rr=0;rr<4;rr++){
            float4 h = *(const float4*)&hs[hf*4+rr][k];
            a1[rr]=fmaf(h.x,n0,a1[rr]); a1[rr]=fmaf(h.y,n1,a1[rr]);
            a1[rr]=fmaf(h.z,n2,a1[rr]); a1[rr]=fmaf(h.w,n3,a1[rr]);
            a2[rr]=fmaf(h.x,c0,a2[rr]); a2[rr]=fmaf(h.y,c1,a2[rr]);
            a2[rr]=fmaf(h.z,c2,a2[rr]); a2[rr]=fmaf(h.w,c3,a2[rr]);
        }
    }
    #pragma unroll
    for(int rr=0;rr<4;rr++){
        int r = hf*4+rr;
        g_NA[(s*DN+d0+r)*PP+p] = a1[rr];
        g_CA[(s*DN+d0+r)*PP+p] = a2[rr];
    }
}

// ---------------------------------------------------------------- logits (t-split, on-the-fly E1)
__global__ void __launch_bounds__(256) k_logits(const float* __restrict__ Wc2,
                                                const float* __restrict__ bc2,
                                                const float* __restrict__ bc1,
                                                float* __restrict__ out){
    int i = blockIdx.x, t0 = blockIdx.y * 8;
    int lane = threadIdx.x & 31, wp = threadIdx.x >> 5;    // 8 warps
    float4 wc = *(const float4*)&Wc2[lane*4];
    float bc2v = bc2[0];
    float4 V4  = *(const float4*)&g_V[lane*4];
    float4 bC4 = *(const float4*)&bc1[lane*4];
    int flag = g_flag;
    float4 na[8];
    #pragma unroll
    for(int t=0;t<8;t++) na[t] = *(const float4*)&g_NA[((t0+t+1)*DN + i)*PP + lane*4];
    int cnt = g_cnt[i];
    for(int k=wp; k<cnt; k+=8){
        int j = g_nbr[i*DN + k];
        float wv = g_nw[i*DN + k];
        float4 e1;
        if(flag){
            e1.x = fmaf(wv, V4.x, bC4.x); e1.y = fmaf(wv, V4.y, bC4.y);
            e1.z = fmaf(wv, V4.z, bC4.z); e1.w = fmaf(wv, V4.w, bC4.w);
        }else{
            e1 = *(const float4*)&g_E1[(i*DN + j)*PP + lane*4];
        }
        #pragma unroll
        for(int t=0;t<8;t++){
            float4 ca = *(const float4*)&g_CA[((t0+t)*DN + j)*PP + lane*4];
            float s;
            s  = fmaxf(na[t].x + ca.x + e1.x, 0.f) * wc.x;
            s += fmaxf(na[t].y + ca.y + e1.y, 0.f) * wc.y;
            s += fmaxf(na[t].z + ca.z + e1.z, 0.f) * wc.z;
            s += fmaxf(na[t].w + ca.w + e1.w, 0.f) * wc.w;
            #pragma unroll
            for(int off=16; off; off>>=1) s += __shfl_xor_sync(0xffffffffu, s, off);
            if(lane == 0) out[(t0+t)*DN*DN + i*DN + j] = s + bc2v;
        }
    }
}

// ---------------------------------------------------------------- dist head (256 thr)
__global__ void __launch_bounds__(256) k_dist(
        const float* __restrict__ Wd1, const float* __restrict__ bd1,
        const float* __restrict__ Wd2, const float* __restrict__ bd2,
        float* __restrict__ out){
    int d0 = blockIdx.x*8, t = blockIdx.y;
    int tid = threadIdx.x, p = tid & 127, hf = tid >> 7;
    __shared__ float df[8][2*PP];
    __shared__ float red[8][PP];
    for(int it=tid; it<8*PP; it+=256){
        int q = it>>3, r = it&7;
        df[r][q]    = g_hg[( t    *DN + d0+r)*PP + q];
        df[r][PP+q] = g_hg[((t+1)*DN + d0+r)*PP + q];
    }
    __syncthreads();
    float acc[4];
    float b = bd1[p];
    #pragma unroll
    for(int r=0;r<4;r++) acc[r] = b;
    #pragma unroll 2
    for(int k=0;k<2*PP;k+=4){
        float w0=Wd1[(k)*PP+p], w1=Wd1[(k+1)*PP+p], w2=Wd1[(k+2)*PP+p], w3=Wd1[(k+3)*PP+p];
        #pragma unroll
        for(int rr=0;rr<4;rr++){
            float4 c = *(const float4*)&df[hf*4+rr][k];
            acc[rr]=fmaf(c.x,w0,acc[rr]); acc[rr]=fmaf(c.y,w1,acc[rr]);
            acc[rr]=fmaf(c.z,w2,acc[rr]); acc[rr]=fmaf(c.w,w3,acc[rr]);
        }
    }
    float wd = Wd2[p];
    #pragma unroll
    for(int rr=0;rr<4;rr++) red[hf*4+rr][p] = fmaxf(acc[rr], 0.f) * wd;
    __syncthreads();
    int r = tid >> 5;                 // 8 warps, warp r reduces row r
    int lane = tid & 31;
    float sv = red[r][lane] + red[r][lane+32] + red[r][lane+64] + red[r][lane+96];
    #pragma unroll
    for(int off=16; off; off>>=1) sv += __shfl_xor_sync(0xffffffffu, sv, off);
    if(lane == 0) out[TM*DN*DN + t*DN + d0 + r] = sv + bd2[0];
}

// ---------------------------------------------------------------- host launcher
extern "C" void kernel_launch(void* const* d_in, const int* in_sizes, int n_in,
                              void* d_out, int out_size){
    struct Exp { int sz; bool opt; };
    static const Exp exp_[23] = {
        {557056,false}, // x
        {16384 ,false}, // edge_w
        {128   ,true }, // batch
        {1     ,true }, // no_graphs
        {2     ,true }, // time_i
        {32768 ,false},{128,false},          // Wn, bn
        {32    ,false},{32 ,false},          // We, be
        {20480 ,false},{128,false},          // Wm, bm
        {32768 ,false},{128,false},          // Wu, bu
        {32768 ,false},{128,false},          // Wg, bg
        {36864 ,false},{128,false},          // Wc1, bc1
        {128   ,false},{1  ,false},          // Wc2, bc2
        {32768 ,false},{128,false},          // Wd1, bd1
        {128   ,false},{1  ,false},          // Wd2, bd2
    };
    const void* ptr[23] = {};
    int pos = 0;
    for(int e=0;e<23;e++){
        if(pos < n_in && in_sizes[pos] == exp_[e].sz){ ptr[e] = d_in[pos]; pos++; }
        else if(exp_[e].opt){ ptr[e] = nullptr; }
        else if(pos < n_in){ ptr[e] = d_in[pos]; pos++; }
    }
    const float* x    = (const float*)ptr[0];
    const float* ew   = (const float*)ptr[1];
    const float* Wn   = (const float*)ptr[5];
    const float* bn   = (const float*)ptr[6];
    const float* We   = (const float*)ptr[7];
    const float* be   = (const float*)ptr[8];
    const float* Wm   = (const float*)ptr[9];
    const float* bm   = (const float*)ptr[10];
    const float* Wu   = (const float*)ptr[11];
    const float* bu   = (const float*)ptr[12];
    const float* Wg   = (const float*)ptr[13];
    const float* bg   = (const float*)ptr[14];
    const float* Wc1  = (const float*)ptr[15];
    const float* bc1  = (const float*)ptr[16];
    const float* Wc2  = (const float*)ptr[17];
    const float* bc2  = (const float*)ptr[18];
    const float* Wd1  = (const float*)ptr[19];
    const float* bd1  = (const float*)ptr[20];
    const float* Wd2  = (const float*)ptr[21];
    const float* bd2  = (const float*)ptr[22];
    float* out = (float*)d_out;

    k_init  <<<512, 128>>>(out);
    k_nbr   <<<DN, 128>>>(ew);
    k_prep  <<<1, 128>>>(We, be, Wm, Wc1);
    k_edgeF <<<DN, 256>>>(We, be, Wm, bm, Wc1, bc1);
    k_encA  <<<dim3(DN/8, TT), 256>>>(x, Wn, bn, Wm);
    k_agg   <<<dim3(DN, 2), 128>>>(bm);
    k_updnc <<<dim3(DN/8, TT), 256>>>(Wu, bu, Wg, bg, Wc1);
    k_logits<<<dim3(DN, 2), 256>>>(Wc2, bc2, bc1, out);
    k_dist  <<<dim3(DN/8, TM), 256>>>(Wd1, bd1, Wd2, bd2, out);
}

// round 5
// speedup vs baseline: 2.4112x; 1.9500x over previous
#include <cuda_runtime.h>

#define TT 17
#define TM 16
#define DN 128
#define HH 256
#define PP 128
#define EE 32
#define MM 128

// scratch (no allocations allowed)
__device__ __align__(16) float g_enc[TT*DN*PP];
__device__ __align__(16) float g_A  [TT*DN*MM];
__device__ __align__(16) float g_hg [TT*DN*PP];
__device__ __align__(16) float g_NA [TT*DN*PP];
__device__ __align__(16) float g_CA [TT*DN*PP];
__device__ __align__(16) float g_U  [MM];
__device__ __align__(16) float g_V  [PP];
__device__ int   g_nbr[DN*DN];
__device__ float g_nw [DN*DN];
__device__ int   g_cnt[DN];
__device__ int   g_flag;   // 1 => be==0, rank-1 edge shortcut valid (modulo per-row w<0 check)

// ================================================================ K1: encA + init + nbr + prep
__global__ void __launch_bounds__(256) k_front(
        const float* __restrict__ x,  const float* __restrict__ Wn,
        const float* __restrict__ bn, const float* __restrict__ Wm,
        const float* __restrict__ ew, const float* __restrict__ We,
        const float* __restrict__ be, const float* __restrict__ Wc1,
        float* __restrict__ out){
    int bx = blockIdx.x, tid = threadIdx.x;

    if(bx < 272){
        // ---------------- encoder + A projection (8 rows, 1 timestep)
        int dt = bx % 16, s = bx / 16, d0 = dt*8;
        int p = tid & 127, hf = tid >> 7;
        __shared__ __align__(16) float xr[8][HH];
        __shared__ __align__(16) float hs[8][PP];
        for(int it=tid; it<8*HH; it+=256){
            int h = it>>3, r = it&7;
            xr[r][h] = x[(s*HH+h)*DN + d0 + r];
        }
        __syncthreads();
        float acc[4];
        float b = bn[p];
        #pragma unroll
        for(int r=0;r<4;r++) acc[r] = b;
        #pragma unroll 4
        for(int k=0;k<HH;k+=4){
            float w0=Wn[(k  )*PP+p], w1=Wn[(k+1)*PP+p];
            float w2=Wn[(k+2)*PP+p], w3=Wn[(k+3)*PP+p];
            #pragma unroll
            for(int rr=0;rr<4;rr++){
                float4 xv = *(const float4*)&xr[hf*4+rr][k];
                acc[rr]=fmaf(xv.x,w0,acc[rr]); acc[rr]=fmaf(xv.y,w1,acc[rr]);
                acc[rr]=fmaf(xv.z,w2,acc[rr]); acc[rr]=fmaf(xv.w,w3,acc[rr]);
            }
        }
        #pragma unroll
        for(int rr=0;rr<4;rr++){
            float v = fmaxf(acc[rr], 0.f);
            g_enc[(s*DN+d0+hf*4+rr)*PP+p] = v;
            hs[hf*4+rr][p] = v;
        }
        __syncthreads();
        float a2[4];
        #pragma unroll
        for(int rr=0;rr<4;rr++) a2[rr] = 0.f;
        #pragma unroll 4
        for(int k=0;k<PP;k+=4){
            float w0=Wm[(k  )*MM+p], w1=Wm[(k+1)*MM+p];
            float w2=Wm[(k+2)*MM+p], w3=Wm[(k+3)*MM+p];
            #pragma unroll
            for(int rr=0;rr<4;rr++){
                float4 hv = *(const float4*)&hs[hf*4+rr][k];
                a2[rr]=fmaf(hv.x,w0,a2[rr]); a2[rr]=fmaf(hv.y,w1,a2[rr]);
                a2[rr]=fmaf(hv.z,w2,a2[rr]); a2[rr]=fmaf(hv.w,w3,a2[rr]);
            }
        }
        #pragma unroll
        for(int rr=0;rr<4;rr++) g_A[(s*DN+d0+hf*4+rr)*MM+p] = a2[rr];
        return;
    }
    bx -= 272;

    if(bx < 256){
        // ---------------- init logits region to -1e9  (256 blk * 256 thr * 16B = 1 MB)
        ((float4*)out)[bx*256 + tid] = make_float4(-1e9f,-1e9f,-1e9f,-1e9f);
        return;
    }
    bx -= 256;

    if(bx < 64){
        // ---------------- neighbor lists, 2 rows per block
        int g = tid >> 7;                    // row group 0/1 within block
        int i = bx*2 + g;
        int j = tid & 127;
        int lane = tid & 31, lw = (tid >> 5) & 3;
        float wv = ew[i*DN + j];
        bool pred = (wv > 0.f) || (j == i);
        unsigned m = __ballot_sync(0xffffffffu, pred);
        __shared__ __align__(16) int wc[2][4];
        if(lane == 0) wc[g][lw] = __popc(m);
        __syncthreads();
        int off = 0;
        for(int t=0;t<lw;t++) off += wc[g][t];
        if(pred){
            int pos = off + __popc(m & ((1u<<lane)-1u));
            g_nbr[i*DN + pos] = j;
            g_nw [i*DN + pos] = wv;
        }
        if(j == 127) g_cnt[i] = off + __popc(m);
        return;
    }

    // ---------------- rank-1 edge precompute + flag (single block)
    {
        int p = tid;
        __shared__ __align__(16) float wes[EE];
        __shared__ int bad;
        if(p == 0) bad = 0;
        __syncthreads();
        if(p < EE){
            wes[p] = fmaxf(We[p], 0.f);
            if(be[p] != 0.f) atomicAdd(&bad, 1);
        }
        __syncthreads();
        if(p < 128){
            float u = 0.f, v = 0.f;
            #pragma unroll
            for(int e=0;e<EE;e++){
                float sc = wes[e];
                u = fmaf(sc, Wm [(PP  + e)*MM + p], u);
                v = fmaf(sc, Wc1[(2*PP+ e)*PP + p], v);
            }
            g_U[p] = u;
            g_V[p] = v;
            if(p == 0) g_flag = (bad == 0) ? 1 : 0;
        }
    }
}

// ================================================================ K2: agg + update/gate + NA/CA (fused)
__global__ void __launch_bounds__(256) k_mid(
        const float* __restrict__ Wu, const float* __restrict__ bu,
        const float* __restrict__ Wg, const float* __restrict__ bg,
        const float* __restrict__ Wc1,const float* __restrict__ bm,
        const float* __restrict__ Wm, const float* __restrict__ We,
        const float* __restrict__ be){
    int bx = blockIdx.x;
    int dt = bx % 16, s = bx / 16, d0 = dt*8;
    int tid = threadIdx.x, p = tid & 127, hf = tid >> 7;

    __shared__ __align__(16) int   js[8][128];
    __shared__ __align__(16) float ws[8][128];
    __shared__ __align__(16) int   cnts[8];
    __shared__ __align__(16) int   rowFb[8];
    __shared__ __align__(16) float cat[8][PP+MM];
    __shared__ __align__(16) float hs[8][PP];

    if(tid < 8){
        cnts[tid]  = g_cnt[d0 + tid];
        rowFb[tid] = g_flag ? 0 : 1;
    }
    __syncthreads();
    for(int it=tid; it<1024; it+=256){
        int r = it>>7, c = it&127;
        int base = (d0+r)*DN + c;
        js[r][c] = g_nbr[base];
        float w = g_nw[base];
        ws[r][c] = w;
        if(c < cnts[r] && w < 0.f) rowFb[r] = 1;
    }
    for(int it=tid; it<8*PP; it+=256){
        int r = it>>7, c = it&127;
        cat[r][c] = g_enc[(s*DN+d0+r)*PP+c];
    }
    __syncthreads();

    // -------- aggregation for 4 rows per thread-half
    float Um = g_U[p], bmm = bm[p];
    #pragma unroll
    for(int rr=0;rr<4;rr++){
        int r = hf*4 + rr;
        int cnt = cnts[r];
        float a = 0.f;
        if(!rowFb[r]){
            for(int k=0;k<cnt;k++){
                int j = js[r][k];
                float b = fmaf(ws[r][k], Um, bmm);
                a = fmaxf(a, g_A[(s*DN + j)*MM + p] + b);
            }
        }else{
            // exact fallback (be != 0 or negative weights) — never taken on this data
            for(int k=0;k<cnt;k++){
                int j = js[r][k];
                float wk = ws[r][k];
                float b = bmm;
                #pragma unroll
                for(int e=0;e<EE;e++){
                    float v = fmaxf(fmaf(wk, We[e], be[e]), 0.f);
                    b = fmaf(v, Wm[(PP+e)*MM + p], b);
                }
                a = fmaxf(a, g_A[(s*DN + j)*MM + p] + b);
            }
        }
        cat[r][PP + p] = a;
    }
    __syncthreads();

    // -------- update + gate
    float u[4], g[4];
    float bup = bu[p], bgp = bg[p];
    #pragma unroll
    for(int r=0;r<4;r++){ u[r]=bup; g[r]=bgp; }
    #pragma unroll 2
    for(int k=0;k<PP+MM;k+=4){
        float u0=Wu[(k)*PP+p], u1=Wu[(k+1)*PP+p], u2=Wu[(k+2)*PP+p], u3=Wu[(k+3)*PP+p];
        float g0=Wg[(k)*PP+p], g1=Wg[(k+1)*PP+p], g2=Wg[(k+2)*PP+p], g3=Wg[(k+3)*PP+p];
        #pragma unroll
        for(int rr=0;rr<4;rr++){
            float4 c = *(const float4*)&cat[hf*4+rr][k];
            u[rr]=fmaf(c.x,u0,u[rr]); u[rr]=fmaf(c.y,u1,u[rr]);
            u[rr]=fmaf(c.z,u2,u[rr]); u[rr]=fmaf(c.w,u3,u[rr]);
            g[rr]=fmaf(c.x,g0,g[rr]); g[rr]=fmaf(c.y,g1,g[rr]);
            g[rr]=fmaf(c.z,g2,g[rr]); g[rr]=fmaf(c.w,g3,g[rr]);
        }
    }
    #pragma unroll
    for(int rr=0;rr<4;rr++){
        int r = hf*4+rr;
        float up = fmaxf(u[rr], 0.f);
        float gg = 1.f / (1.f + __expf(-g[rr]));
        float hv = gg*up + (1.f - gg)*cat[r][p];
        g_hg[(s*DN+d0+r)*PP+p] = hv;
        hs[r][p] = hv;
    }
    __syncthreads();

    // -------- NA / CA projections
    float a1[4], a2[4];
    #pragma unroll
    for(int r=0;r<4;r++){ a1[r]=0.f; a2[r]=0.f; }
    #pragma unroll 2
    for(int k=0;k<PP;k+=4){
        float n0=Wc1[(k)*PP+p], n1=Wc1[(k+1)*PP+p], n2=Wc1[(k+2)*PP+p], n3=Wc1[(k+3)*PP+p];
        float c0=Wc1[(PP+k)*PP+p], c1=Wc1[(PP+k+1)*PP+p], c2=Wc1[(PP+k+2)*PP+p], c3=Wc1[(PP+k+3)*PP+p];
        #pragma unroll
        for(int rr=0;rr<4;rr++){
            float4 h = *(const float4*)&hs[hf*4+rr][k];
            a1[rr]=fmaf(h.x,n0,a1[rr]); a1[rr]=fmaf(h.y,n1,a1[rr]);
            a1[rr]=fmaf(h.z,n2,a1[rr]); a1[rr]=fmaf(h.w,n3,a1[rr]);
            a2[rr]=fmaf(h.x,c0,a2[rr]); a2[rr]=fmaf(h.y,c1,a2[rr]);
            a2[rr]=fmaf(h.z,c2,a2[rr]); a2[rr]=fmaf(h.w,c3,a2[rr]);
        }
    }
    #pragma unroll
    for(int rr=0;rr<4;rr++){
        int r = hf*4+rr;
        g_NA[(s*DN+d0+r)*PP+p] = a1[rr];
        g_CA[(s*DN+d0+r)*PP+p] = a2[rr];
    }
}

// ================================================================ K3: logits + dist
__global__ void __launch_bounds__(256) k_back(
        const float* __restrict__ Wc1,const float* __restrict__ Wc2,
        const float* __restrict__ bc2,const float* __restrict__ bc1,
        const float* __restrict__ We, const float* __restrict__ be,
        const float* __restrict__ Wd1,const float* __restrict__ bd1,
        const float* __restrict__ Wd2,const float* __restrict__ bd2,
        float* __restrict__ out){
    int bx = blockIdx.x, tid = threadIdx.x;

    if(bx < 256){
        // ---------------- logits: node i, 8 timesteps
        int i = bx & 127, t0 = (bx >> 7) * 8;
        int lane = tid & 31, wp = tid >> 5;
        __shared__ __align__(16) int   js[128];
        __shared__ __align__(16) float ws[128];
        __shared__ __align__(16) int   sFb[4];   // [0]=fallback flag, [1]=cnt (16B-padded)
        if(tid == 0){ sFb[1] = g_cnt[i]; sFb[0] = g_flag ? 0 : 1; }
        __syncthreads();
        int cnt = sFb[1];
        if(tid < 128){
            js[tid] = g_nbr[i*DN + tid];
            float w = g_nw[i*DN + tid];
            ws[tid] = w;
            if(tid < cnt && w < 0.f) sFb[0] = 1;
        }
        __syncthreads();

        float4 wc  = *(const float4*)&Wc2[lane*4];
        float bc2v = bc2[0];
        float4 V4  = *(const float4*)&g_V[lane*4];
        float4 bC4 = *(const float4*)&bc1[lane*4];
        int fb = sFb[0];
        float4 na[8];
        #pragma unroll
        for(int t=0;t<8;t++) na[t] = *(const float4*)&g_NA[((t0+t+1)*DN + i)*PP + lane*4];

        for(int k=wp; k<cnt; k+=8){
            int j = js[k];
            float wv = ws[k];
            float4 e1;
            if(!fb){
                e1.x = fmaf(wv, V4.x, bC4.x); e1.y = fmaf(wv, V4.y, bC4.y);
                e1.z = fmaf(wv, V4.z, bC4.z); e1.w = fmaf(wv, V4.w, bC4.w);
            }else{
                e1 = bC4;
                #pragma unroll
                for(int e=0;e<EE;e++){
                    float v = fmaxf(fmaf(wv, We[e], be[e]), 0.f);
                    e1.x = fmaf(v, Wc1[(2*PP+e)*PP + lane*4 + 0], e1.x);
                    e1.y = fmaf(v, Wc1[(2*PP+e)*PP + lane*4 + 1], e1.y);
                    e1.z = fmaf(v, Wc1[(2*PP+e)*PP + lane*4 + 2], e1.z);
                    e1.w = fmaf(v, Wc1[(2*PP+e)*PP + lane*4 + 3], e1.w);
                }
            }
            #pragma unroll
            for(int t=0;t<8;t++){
                float4 ca = *(const float4*)&g_CA[((t0+t)*DN + j)*PP + lane*4];
                float s;
                s  = fmaxf(na[t].x + ca.x + e1.x, 0.f) * wc.x;
                s += fmaxf(na[t].y + ca.y + e1.y, 0.f) * wc.y;
                s += fmaxf(na[t].z + ca.z + e1.z, 0.f) * wc.z;
                s += fmaxf(na[t].w + ca.w + e1.w, 0.f) * wc.w;
                #pragma unroll
                for(int off=16; off; off>>=1) s += __shfl_xor_sync(0xffffffffu, s, off);
                if(lane == 0) out[(t0+t)*DN*DN + i*DN + j] = s + bc2v;
            }
        }
        return;
    }
    bx -= 256;

    // ---------------- dist head: 8 nodes, 1 timestep
    {
        int dt = bx % 16, t = bx / 16, d0 = dt*8;
        int p = tid & 127, hf = tid >> 7;
        __shared__ __align__(16) float df[8][2*PP];
        __shared__ __align__(16) float red[8][PP];
        for(int it=tid; it<8*PP; it+=256){
            int q = it>>3, r = it&7;
            df[r][q]    = g_hg[( t    *DN + d0+r)*PP + q];
            df[r][PP+q] = g_hg[((t+1)*DN + d0+r)*PP + q];
        }
        __syncthreads();
        float acc[4];
        float b = bd1[p];
        #pragma unroll
        for(int r=0;r<4;r++) acc[r] = b;
        #pragma unroll 2
        for(int k=0;k<2*PP;k+=4){
            float w0=Wd1[(k)*PP+p], w1=Wd1[(k+1)*PP+p], w2=Wd1[(k+2)*PP+p], w3=Wd1[(k+3)*PP+p];
            #pragma unroll
            for(int rr=0;rr<4;rr++){
                float4 c = *(const float4*)&df[hf*4+rr][k];
                acc[rr]=fmaf(c.x,w0,acc[rr]); acc[rr]=fmaf(c.y,w1,acc[rr]);
                acc[rr]=fmaf(c.z,w2,acc[rr]); acc[rr]=fmaf(c.w,w3,acc[rr]);
            }
        }
        float wd = Wd2[p];
        #pragma unroll
        for(int rr=0;rr<4;rr++) red[hf*4+rr][p] = fmaxf(acc[rr], 0.f) * wd;
        __syncthreads();
        int r = tid >> 5;
        int lane = tid & 31;
        float sv = red[r][lane] + red[r][lane+32] + red[r][lane+64] + red[r][lane+96];
        #pragma unroll
        for(int off=16; off; off>>=1) sv += __shfl_xor_sync(0xffffffffu, sv, off);
        if(lane == 0) out[TM*DN*DN + t*DN + d0 + r] = sv + bd2[0];
    }
}

// ================================================================ host launcher
extern "C" void kernel_launch(void* const* d_in, const int* in_sizes, int n_in,
                              void* d_out, int out_size){
    struct Exp { int sz; bool opt; };
    static const Exp exp_[23] = {
        {557056,false}, // x
        {16384 ,false}, // edge_w
        {128   ,true }, // batch
        {1     ,true }, // no_graphs
        {2     ,true }, // time_i
        {32768 ,false},{128,false},          // Wn, bn
        {32    ,false},{32 ,false},          // We, be
        {20480 ,false},{128,false},          // Wm, bm
        {32768 ,false},{128,false},          // Wu, bu
        {32768 ,false},{128,false},          // Wg, bg
        {36864 ,false},{128,false},          // Wc1, bc1
        {128   ,false},{1  ,false},          // Wc2, bc2
        {32768 ,false},{128,false},          // Wd1, bd1
        {128   ,false},{1  ,false},          // Wd2, bd2
    };
    const void* ptr[23] = {};
    int pos = 0;
    for(int e=0;e<23;e++){
        if(pos < n_in && in_sizes[pos] == exp_[e].sz){ ptr[e] = d_in[pos]; pos++; }
        else if(exp_[e].opt){ ptr[e] = nullptr; }
        else if(pos < n_in){ ptr[e] = d_in[pos]; pos++; }
    }
    const float* x    = (const float*)ptr[0];
    const float* ew   = (const float*)ptr[1];
    const float* Wn   = (const float*)ptr[5];
    const float* bn   = (const float*)ptr[6];
    const float* We   = (const float*)ptr[7];
    const float* be   = (const float*)ptr[8];
    const float* Wm   = (const float*)ptr[9];
    const float* bm   = (const float*)ptr[10];
    const float* Wu   = (const float*)ptr[11];
    const float* bu   = (const float*)ptr[12];
    const float* Wg   = (const float*)ptr[13];
    const float* bg   = (const float*)ptr[14];
    const float* Wc1  = (const float*)ptr[15];
    const float* bc1  = (const float*)ptr[16];
    const float* Wc2  = (const float*)ptr[17];
    const float* bc2  = (const float*)ptr[18];
    const float* Wd1  = (const float*)ptr[19];
    const float* bd1  = (const float*)ptr[20];
    const float* Wd2  = (const float*)ptr[21];
    const float* bd2  = (const float*)ptr[22];
    float* out = (float*)d_out;

    k_front<<<272 + 256 + 64 + 1, 256>>>(x, Wn, bn, Wm, ew, We, be, Wc1, out);
    k_mid  <<<272, 256>>>(Wu, bu, Wg, bg, Wc1, bm, Wm, We, be);
    k_back <<<512, 256>>>(Wc1, Wc2, bc2, bc1, We, be, Wd1, bd1, Wd2, bd2, out);
}